// round 8
// baseline (speedup 1.0000x reference)
#include <cuda_runtime.h>
#include <cuda_bf16.h>
#include <cstdint>

// B=32, W=256, N=512, thresholds {0.3,0.5,0.7}
// out: (B,6) fp32 [t0_b0,t0_b1,t1_b0,t1_b1,t2_b0,t2_b1]

#define BATCH 32
#define WIN   256
#define NA    512
#define CAP   131072   // >= 512*511/2
#define WSPL  4
#define KCH   64       // bf16 per K-chunk (128 B rows)
#define NCH   12       // 768 / 64
#define NSTG  3
#define STAGE_BYTES 16384   // 8KB A(64 rows) + 8KB B(64 rows)
#define SMEM_DYN    (NSTG * STAGE_BYTES)   // 48 KB -> 4 CTAs/SM
#define NTILE 36            // upper-tri 8x8 of 64-blocks

// ---------------- device scratch ----------------
__device__ float g_psum [WSPL][BATCH][NA];
__device__ float g_psum2[WSPL][BATCH][NA];
__device__ __nv_bfloat16 g_h[BATCH][NA][WIN];   // 8 MB
__device__ __nv_bfloat16 g_r[BATCH][NA][WIN];   // 8 MB
__device__ int   g_ecnt[3][BATCH];
__device__ unsigned int g_edges[3][BATCH][CAP];

__device__ __forceinline__ uint32_t smem_u32(const void* p) {
    uint32_t a;
    asm("{ .reg .u64 t; cvta.to.shared.u64 t, %1; cvt.u32.u64 %0, t; }" : "=r"(a) : "l"(p));
    return a;
}
#define SW128(x) ((x) ^ (((x) >> 3) & 0x70))
#define CP16(dst, src) \
    asm volatile("cp.async.cg.shared.global [%0], [%1], 16;" :: "r"(dst), "l"(src))
#define CPCOMMIT() asm volatile("cp.async.commit_group;" ::: "memory")
#define CPWAIT1()  asm volatile("cp.async.wait_group 1;" ::: "memory")
#define CPWAIT0()  asm volatile("cp.async.wait_group 0;" ::: "memory")

// ---------------- stats stage 1 (+zero edge counters) ----------------
__global__ void stats1_kernel(const float* __restrict__ ret) {
    int n = blockIdx.x * 128 + threadIdx.x;
    int b = blockIdx.y;
    int wc = blockIdx.z * (WIN / WSPL);
    if (blockIdx.x == 0 && b == 0 && blockIdx.z == 0 && threadIdx.x < 96)
        ((int*)g_ecnt)[threadIdx.x] = 0;
    const float* col = ret + (size_t)b * WIN * NA + (size_t)wc * NA + n;
    float s = 0.f, s2 = 0.f;
#pragma unroll 16
    for (int w = 0; w < WIN / WSPL; w++) {
        float x = col[(size_t)w * NA];
        s += x; s2 += x * x;
    }
    g_psum [blockIdx.z][b][n] = s;
    g_psum2[blockIdx.z][b][n] = s2;
}

// ---------------- convert: inline stats2 + normalize + bf16 split + transpose
__global__ void convert_kernel(const float* __restrict__ ret) {
    __shared__ float tile[32][33];
    int b = blockIdx.z, n0 = blockIdx.x * 32, w0 = blockIdx.y * 32;
    int tx = threadIdx.x, ty = threadIdx.y;   // (32,8)
#pragma unroll
    for (int rr = 0; rr < 4; rr++) {
        int wl = ty * 4 + rr;
        tile[wl][tx] = ret[((size_t)b * WIN + (w0 + wl)) * NA + n0 + tx];
    }
    __syncthreads();
#pragma unroll
    for (int rr = 0; rr < 4; rr++) {
        int nl = ty * 4 + rr;
        int n = n0 + nl, w = w0 + tx;
        float s = 0.f, s2 = 0.f;
#pragma unroll
        for (int k = 0; k < WSPL; k++) { s += g_psum[k][b][n]; s2 += g_psum2[k][b][n]; }
        float mean = s * (1.0f / WIN);
        float var = fmaxf((s2 - s * mean) * (1.0f / (WIN - 1)), 0.0f);
        float invstd = 1.0f / (sqrtf(var) + 1e-8f);
        float x = (tile[tx][nl] - mean) * invstd;
        __nv_bfloat16 h = __float2bfloat16(x);
        __nv_bfloat16 r = __float2bfloat16(x - __bfloat162float(h));
        g_h[b][n][w] = h;
        g_r[b][n][w] = r;
    }
}

// ---------------- corr GEMM: mma.sync bf16 3-term split, 3-stage cp.async ----
// A-role K: [h, r, h] ; B-role K: [h, h, r]  ->  A.B = h.h + r.h + h.r
// CTA tile 64x64, 128 threads = 4 warps (2x2), warp tile 32x32.
// Grid: 36 upper-tri 64-tiles x 32 batches = 1152 CTAs, ~4/SM resident.
__global__ void __launch_bounds__(128, 4)
corr_mma_kernel() {
    extern __shared__ __align__(128) unsigned char dsm[];
    const uint32_t sb = smem_u32(dsm);

    const int TI[NTILE] = {0,0,0,0,0,0,0,0, 1,1,1,1,1,1,1, 2,2,2,2,2,2,
                           3,3,3,3,3, 4,4,4,4, 5,5,5, 6,6, 7};
    const int TJ[NTILE] = {0,1,2,3,4,5,6,7, 1,2,3,4,5,6,7, 2,3,4,5,6,7,
                           3,4,5,6,7, 4,5,6,7, 5,6,7, 6,7, 7};
    const int b  = blockIdx.y;
    const int i0 = TI[blockIdx.x] * 64;
    const int j0 = TJ[blockIdx.x] * 64;
    const int t = threadIdx.x;
    const int wid = t >> 5, lane = t & 31;
    const int mw = wid >> 1;       // 0..1 : 32-row group
    const int nw = wid & 1;        // 0..1 : 32-col group

    float acc[2][4][4];
#pragma unroll
    for (int mt = 0; mt < 2; mt++)
#pragma unroll
        for (int nt = 0; nt < 4; nt++)
#pragma unroll
            for (int q = 0; q < 4; q++) acc[mt][nt][q] = 0.f;

    // fill: thread t -> row t/2 (0..63), half t&1 (64 B = 4x16B); same for A and B
    const int frow = t >> 1, fhalf = t & 1;
    const uint32_t fswz = SW128(frow * 128 + fhalf * 64);

    const __nv_bfloat16* rowAh = &g_h[b][i0 + frow][0];
    const __nv_bfloat16* rowAr = &g_r[b][i0 + frow][0];
    const __nv_bfloat16* rowBh = &g_h[b][j0 + frow][0];
    const __nv_bfloat16* rowBr = &g_r[b][j0 + frow][0];

    auto load_chunk = [&](int c) {
        const int st = c % NSTG;
        const uint32_t base = sb + st * STAGE_BYTES;
        const int col = (c & 3) * KCH + fhalf * 32;
        const __nv_bfloat16* sA = (c < 4 || c >= 8) ? rowAh + col : rowAr + col;
        const __nv_bfloat16* sB = (c < 8) ? rowBh + col : rowBr + col;
#pragma unroll
        for (int f = 0; f < 4; f++) {
            CP16(base + (fswz ^ (f * 16)), sA + f * 8);
            CP16(base + 8192 + (fswz ^ (f * 16)), sB + f * 8);
        }
        CPCOMMIT();
    };

    load_chunk(0);
    load_chunk(1);

    for (int c = 0; c < NCH; c++) {
        if (c < NCH - 1) CPWAIT1(); else CPWAIT0();
        __syncthreads();

        const uint32_t sbA = sb + (c % NSTG) * STAGE_BYTES;
        const uint32_t sbB = sbA + 8192;
#pragma unroll
        for (int ks = 0; ks < 4; ks++) {
            const int kb = ks * 32;
            uint32_t af[2][4];
#pragma unroll
            for (int mt = 0; mt < 2; mt++) {
                int row = mw * 32 + mt * 16 + ((lane >> 3) & 1) * 8 + (lane & 7);
                int kbyte = kb + (lane >> 4) * 16;
                uint32_t addr = sbA + SW128(row * 128 + kbyte);
                asm volatile("ldmatrix.sync.aligned.m8n8.x4.shared.b16 {%0,%1,%2,%3}, [%4];"
                    : "=r"(af[mt][0]), "=r"(af[mt][1]), "=r"(af[mt][2]), "=r"(af[mt][3])
                    : "r"(addr));
            }
            uint32_t bf[4][2];
#pragma unroll
            for (int np = 0; np < 2; np++) {
                int row = nw * 32 + np * 16 + ((lane >> 4) & 1) * 8 + (lane & 7);
                int kbyte = kb + ((lane >> 3) & 1) * 16;
                uint32_t addr = sbB + SW128(row * 128 + kbyte);
                asm volatile("ldmatrix.sync.aligned.m8n8.x4.shared.b16 {%0,%1,%2,%3}, [%4];"
                    : "=r"(bf[2*np][0]), "=r"(bf[2*np][1]),
                      "=r"(bf[2*np+1][0]), "=r"(bf[2*np+1][1])
                    : "r"(addr));
            }
#pragma unroll
            for (int mt = 0; mt < 2; mt++)
#pragma unroll
                for (int nt = 0; nt < 4; nt++)
                    asm volatile(
                        "mma.sync.aligned.m16n8k16.row.col.f32.bf16.bf16.f32 "
                        "{%0,%1,%2,%3}, {%4,%5,%6,%7}, {%8,%9}, {%0,%1,%2,%3};"
                        : "+f"(acc[mt][nt][0]), "+f"(acc[mt][nt][1]),
                          "+f"(acc[mt][nt][2]), "+f"(acc[mt][nt][3])
                        : "r"(af[mt][0]), "r"(af[mt][1]), "r"(af[mt][2]), "r"(af[mt][3]),
                          "r"(bf[nt][0]), "r"(bf[nt][1]));
        }

        if (c + 2 < NCH) load_chunk(c + 2);
        else CPCOMMIT();   // keep group accounting uniform
    }

    // epilogue: threshold -> edge lists (gi<gj, each edge once)
#pragma unroll
    for (int mt = 0; mt < 2; mt++) {
#pragma unroll
        for (int nt = 0; nt < 4; nt++) {
            int gi0 = i0 + mw * 32 + mt * 16 + (lane >> 2);
            int gj0 = j0 + nw * 32 + nt * 8 + 2 * (lane & 3);
#pragma unroll
            for (int q = 0; q < 4; q++) {
                int gi = gi0 + (q >> 1) * 8;
                int gj = gj0 + (q & 1);
                float v = fabsf(acc[mt][nt][q] * (1.0f / 256.0f));
                if (gi < gj && v > 0.3f) {
                    unsigned int e = ((unsigned int)gi << 16) | (unsigned int)gj;
                    int p0 = atomicAdd(&g_ecnt[0][b], 1);
                    g_edges[0][b][p0] = e;
                    if (v > 0.5f) {
                        int p1 = atomicAdd(&g_ecnt[1][b], 1);
                        g_edges[1][b][p1] = e;
                        if (v > 0.7f) {
                            int p2 = atomicAdd(&g_ecnt[2][b], 1);
                            g_edges[2][b][p2] = e;
                        }
                    }
                }
            }
        }
    }
}

// ---------------- components + Betti ----------------
__global__ void __launch_bounds__(512, 1)
betti_kernel(float* __restrict__ out) {
    __shared__ int label[NA];
    __shared__ int changed;
    __shared__ int comp_cnt;

    const int tt = blockIdx.x >> 5;
    const int b  = blockIdx.x & 31;
    const int tid = threadIdx.x;

    const int cnt = g_ecnt[tt][b];
    const unsigned int* el = &g_edges[tt][b][0];

    label[tid] = tid;
    if (tid == 0) comp_cnt = 0;

    while (true) {
        __syncthreads();
        if (tid == 0) changed = 0;
        __syncthreads();
        for (int e = tid; e < cnt; e += NA) {
            unsigned int pk = el[e];
            int i = pk >> 16, j = pk & 0xFFFF;
            int li = label[i], lj = label[j];
            if (li < lj) { atomicMin(&label[j], li); changed = 1; }
            else if (lj < li) { atomicMin(&label[i], lj); changed = 1; }
        }
        __syncthreads();
        int l = label[tid];
        int ll = label[l];
        if (ll < l) { label[tid] = ll; changed = 1; }
        __syncthreads();
        if (!changed) break;
    }

    int isrep = (label[tid] == tid) ? 1 : 0;
#pragma unroll
    for (int o = 16; o; o >>= 1) isrep += __shfl_down_sync(0xFFFFFFFFu, isrep, o);
    if ((tid & 31) == 0) atomicAdd(&comp_cnt, isrep);
    __syncthreads();

    if (tid == 0) {
        float comp = (float)comp_cnt;
        float b1 = fmaxf(0.0f, (float)cnt - (float)NA + comp);
        out[b * 6 + tt * 2 + 0] = comp * (1.0f / NA);
        out[b * 6 + tt * 2 + 1] = b1 * (1.0f / NA);
    }
}

// ---------------- launch ----------------
extern "C" void kernel_launch(void* const* d_in, const int* in_sizes, int n_in,
                              void* d_out, int out_size) {
    const float* ret = (const float*)d_in[0];
    float* out = (float*)d_out;
    (void)in_sizes; (void)n_in; (void)out_size;

    cudaFuncSetAttribute(corr_mma_kernel,
                         cudaFuncAttributeMaxDynamicSharedMemorySize, SMEM_DYN);

    { dim3 g(NA / 128, BATCH, WSPL); stats1_kernel<<<g, 128>>>(ret); }
    { dim3 g(NA / 32, WIN / 32, BATCH); dim3 blk(32, 8); convert_kernel<<<g, blk>>>(ret); }
    { dim3 g(NTILE, BATCH);          corr_mma_kernel<<<g, 128, SMEM_DYN>>>(); }
    betti_kernel<<<96, 512>>>(out);
}

// round 9
// speedup vs baseline: 1.0522x; 1.0522x over previous
#include <cuda_runtime.h>
#include <cuda_bf16.h>
#include <cstdint>

// B=32, W=256, N=512, thresholds {0.3,0.5,0.7}
// out: (B,6) fp32 [t0_b0,t0_b1,t1_b0,t1_b1,t2_b0,t2_b1]

#define BATCH 32
#define WIN   256
#define NA    512
#define CAP   131072   // >= 512*511/2
#define KCH   64       // bf16 per K-chunk (128 B rows)
#define NCH   12       // 768 / 64
#define NSTG  3
#define STAGE_BYTES 24576   // 16KB A(128 rows) + 8KB B(64 rows)
#define SMEM_DYN    (NSTG * STAGE_BYTES)
#define NTILE 20
#define CONV_SMEM (WIN * 65 * 4)   // 66560 B: fp32 tile [256][65]

// ---------------- device scratch ----------------
__device__ __nv_bfloat16 g_h[BATCH][NA][WIN];   // 8 MB
__device__ __nv_bfloat16 g_r[BATCH][NA][WIN];   // 8 MB
__device__ int   g_ecnt[3][BATCH];
__device__ unsigned int g_edges[3][BATCH][CAP];

__device__ __forceinline__ uint32_t smem_u32(const void* p) {
    uint32_t a;
    asm("{ .reg .u64 t; cvta.to.shared.u64 t, %1; cvt.u32.u64 %0, t; }" : "=r"(a) : "l"(p));
    return a;
}
#define SW128(x) ((x) ^ (((x) >> 3) & 0x70))
#define CP16(dst, src) \
    asm volatile("cp.async.cg.shared.global [%0], [%1], 16;" :: "r"(dst), "l"(src))
#define CPCOMMIT() asm volatile("cp.async.commit_group;" ::: "memory")
#define CPWAIT1()  asm volatile("cp.async.wait_group 1;" ::: "memory")
#define CPWAIT0()  asm volatile("cp.async.wait_group 0;" ::: "memory")

// ------- fused stats + normalize + bf16 split + transpose (single input pass)
// grid (8 n-chunks, 32 b), 256 threads; thread = (asset a = t&63, quarter q = t>>6)
__global__ void __launch_bounds__(256)
fused_convert_kernel(const float* __restrict__ ret) {
    extern __shared__ float fsm[];               // [256][65] fp32
    __shared__ float ps[4][64], ps2[4][64], mean_s[64], inv_s[64];

    const int b = blockIdx.y, n0 = blockIdx.x * 64;
    const int t = threadIdx.x;
    const int a = t & 63, q = t >> 6;

    if (blockIdx.x == 0 && b == 0 && t < 96)
        ((int*)g_ecnt)[t] = 0;

    // load 64 assets x 256 w, coalesced (4 w-rows per iteration)
    const float* src = ret + (size_t)b * WIN * NA + n0;
    for (int w0 = 0; w0 < WIN; w0 += 4) {
        int w = w0 + q;
        fsm[w * 65 + a] = src[(size_t)w * NA + a];
    }
    __syncthreads();

    // per-(asset, quarter) partial sums, w ascending (same order as before)
    float s = 0.f, s2 = 0.f;
#pragma unroll 16
    for (int i = 0; i < 64; i++) {
        float x = fsm[(q * 64 + i) * 65 + a];
        s += x; s2 += x * x;
    }
    ps[q][a] = s; ps2[q][a] = s2;
    __syncthreads();

    if (q == 0) {
        float ss  = ((ps [0][a] + ps [1][a]) + ps [2][a]) + ps [3][a];
        float ss2 = ((ps2[0][a] + ps2[1][a]) + ps2[2][a]) + ps2[3][a];
        float mean = ss * (1.0f / WIN);
        float var = fmaxf((ss2 - ss * mean) * (1.0f / (WIN - 1)), 0.0f);
        mean_s[a] = mean;
        inv_s[a] = 1.0f / (sqrtf(var) + 1e-8f);
    }
    __syncthreads();

    const float mean = mean_s[a], inv = inv_s[a];
    const int n = n0 + a;
    __nv_bfloat16* dh = &g_h[b][n][q * 64];
    __nv_bfloat16* dr = &g_r[b][n][q * 64];
#pragma unroll
    for (int w8 = 0; w8 < 64; w8 += 8) {
        unsigned int hw[4], rw[4];
#pragma unroll
        for (int k = 0; k < 4; k++) {
            int w = q * 64 + w8 + 2 * k;
            float x0 = (fsm[w * 65 + a] - mean) * inv;
            float x1 = (fsm[(w + 1) * 65 + a] - mean) * inv;
            __nv_bfloat16 h0 = __float2bfloat16(x0);
            __nv_bfloat16 h1 = __float2bfloat16(x1);
            __nv_bfloat16 r0 = __float2bfloat16(x0 - __bfloat162float(h0));
            __nv_bfloat16 r1 = __float2bfloat16(x1 - __bfloat162float(h1));
            hw[k] = ((unsigned int)__bfloat16_as_ushort(h1) << 16) | __bfloat16_as_ushort(h0);
            rw[k] = ((unsigned int)__bfloat16_as_ushort(r1) << 16) | __bfloat16_as_ushort(r0);
        }
        *(uint4*)(dh + w8) = make_uint4(hw[0], hw[1], hw[2], hw[3]);
        *(uint4*)(dr + w8) = make_uint4(rw[0], rw[1], rw[2], rw[3]);
    }
}

// ---------------- corr GEMM: mma.sync bf16 3-term split, 3-stage cp.async ----
// A-role K: [h, r, h] ; B-role K: [h, h, r]  ->  A.B = h.h + r.h + h.r
// CTA tile 128x64, 8 warps (4x2), warp tile 32x32. Grid: 20 upper-tri tiles x 32 b.
__global__ void __launch_bounds__(256, 3)
corr_mma_kernel() {
    extern __shared__ __align__(128) unsigned char dsm[];
    const uint32_t sb = smem_u32(dsm);

    const int TI[NTILE] = {0,0,0,0,0,0,0,0, 1,1,1,1,1,1, 2,2,2,2, 3,3};
    const int TJ[NTILE] = {0,1,2,3,4,5,6,7, 2,3,4,5,6,7, 4,5,6,7, 6,7};
    const int b  = blockIdx.y;
    const int i0 = TI[blockIdx.x] * 128;
    const int j0 = TJ[blockIdx.x] * 64;
    const int t = threadIdx.x;
    const int wid = t >> 5, lane = t & 31;
    const int mw = wid >> 1;       // 0..3 : 32-row group
    const int nw = wid & 1;        // 0..1 : 32-col group

    float acc[2][4][4];
#pragma unroll
    for (int mt = 0; mt < 2; mt++)
#pragma unroll
        for (int nt = 0; nt < 4; nt++)
#pragma unroll
            for (int q = 0; q < 4; q++) acc[mt][nt][q] = 0.f;

    // A fill: thread t -> row t/2 (0..127), half t&1 (64 B = 4x16B)
    const int arow = t >> 1, ahalf = t & 1;
    const uint32_t aswz = SW128(arow * 128 + ahalf * 64);
    // B fill: thread t -> row t/4 (0..63), quarter t&3 (32 B = 2x16B)
    const int brow = t >> 2, bq = t & 3;
    const uint32_t bswz = SW128(brow * 128 + bq * 32);

    const __nv_bfloat16* rowAh = &g_h[b][i0 + arow][0];
    const __nv_bfloat16* rowAr = &g_r[b][i0 + arow][0];
    const __nv_bfloat16* rowBh = &g_h[b][j0 + brow][0];
    const __nv_bfloat16* rowBr = &g_r[b][j0 + brow][0];

    auto load_chunk = [&](int c) {
        const int st = c % NSTG;
        const uint32_t base = sb + st * STAGE_BYTES;
        const int colA = (c & 3) * KCH + ahalf * 32;
        const __nv_bfloat16* sA = (c < 4 || c >= 8) ? rowAh + colA : rowAr + colA;
#pragma unroll
        for (int f = 0; f < 4; f++)
            CP16(base + (aswz ^ (f * 16)), sA + f * 8);
        const int colB = (c & 3) * KCH + bq * 16;
        const __nv_bfloat16* sB = (c < 8) ? rowBh + colB : rowBr + colB;
        CP16(base + 16384 + bswz, sB);
        CP16(base + 16384 + (bswz ^ 16), sB + 8);
        CPCOMMIT();
    };

    load_chunk(0);
    load_chunk(1);

    for (int c = 0; c < NCH; c++) {
        if (c < NCH - 1) CPWAIT1(); else CPWAIT0();
        __syncthreads();

        const uint32_t sbA = sb + (c % NSTG) * STAGE_BYTES;
        const uint32_t sbB = sbA + 16384;
#pragma unroll
        for (int ks = 0; ks < 4; ks++) {
            const int kb = ks * 32;
            uint32_t af[2][4];
#pragma unroll
            for (int mt = 0; mt < 2; mt++) {
                int row = mw * 32 + mt * 16 + ((lane >> 3) & 1) * 8 + (lane & 7);
                int kbyte = kb + (lane >> 4) * 16;
                uint32_t addr = sbA + SW128(row * 128 + kbyte);
                asm volatile("ldmatrix.sync.aligned.m8n8.x4.shared.b16 {%0,%1,%2,%3}, [%4];"
                    : "=r"(af[mt][0]), "=r"(af[mt][1]), "=r"(af[mt][2]), "=r"(af[mt][3])
                    : "r"(addr));
            }
            uint32_t bf[4][2];
#pragma unroll
            for (int np = 0; np < 2; np++) {
                int row = nw * 32 + np * 16 + ((lane >> 4) & 1) * 8 + (lane & 7);
                int kbyte = kb + ((lane >> 3) & 1) * 16;
                uint32_t addr = sbB + SW128(row * 128 + kbyte);
                asm volatile("ldmatrix.sync.aligned.m8n8.x4.shared.b16 {%0,%1,%2,%3}, [%4];"
                    : "=r"(bf[2*np][0]), "=r"(bf[2*np][1]),
                      "=r"(bf[2*np+1][0]), "=r"(bf[2*np+1][1])
                    : "r"(addr));
            }
#pragma unroll
            for (int mt = 0; mt < 2; mt++)
#pragma unroll
                for (int nt = 0; nt < 4; nt++)
                    asm volatile(
                        "mma.sync.aligned.m16n8k16.row.col.f32.bf16.bf16.f32 "
                        "{%0,%1,%2,%3}, {%4,%5,%6,%7}, {%8,%9}, {%0,%1,%2,%3};"
                        : "+f"(acc[mt][nt][0]), "+f"(acc[mt][nt][1]),
                          "+f"(acc[mt][nt][2]), "+f"(acc[mt][nt][3])
                        : "r"(af[mt][0]), "r"(af[mt][1]), "r"(af[mt][2]), "r"(af[mt][3]),
                          "r"(bf[nt][0]), "r"(bf[nt][1]));
        }

        if (c + 2 < NCH) load_chunk(c + 2);
        else CPCOMMIT();   // keep group accounting uniform
    }

    // epilogue: threshold -> edge lists (gi<gj, each edge once)
#pragma unroll
    for (int mt = 0; mt < 2; mt++) {
#pragma unroll
        for (int nt = 0; nt < 4; nt++) {
            int gi0 = i0 + mw * 32 + mt * 16 + (lane >> 2);
            int gj0 = j0 + nw * 32 + nt * 8 + 2 * (lane & 3);
#pragma unroll
            for (int q = 0; q < 4; q++) {
                int gi = gi0 + (q >> 1) * 8;
                int gj = gj0 + (q & 1);
                float v = fabsf(acc[mt][nt][q] * (1.0f / 256.0f));
                if (gi < gj && v > 0.3f) {
                    unsigned int e = ((unsigned int)gi << 16) | (unsigned int)gj;
                    int p0 = atomicAdd(&g_ecnt[0][b], 1);
                    g_edges[0][b][p0] = e;
                    if (v > 0.5f) {
                        int p1 = atomicAdd(&g_ecnt[1][b], 1);
                        g_edges[1][b][p1] = e;
                        if (v > 0.7f) {
                            int p2 = atomicAdd(&g_ecnt[2][b], 1);
                            g_edges[2][b][p2] = e;
                        }
                    }
                }
            }
        }
    }
}

// ---------------- components + Betti ----------------
__global__ void __launch_bounds__(512, 1)
betti_kernel(float* __restrict__ out) {
    __shared__ int label[NA];
    __shared__ int changed;
    __shared__ int comp_cnt;

    const int tt = blockIdx.x >> 5;
    const int b  = blockIdx.x & 31;
    const int tid = threadIdx.x;

    const int cnt = g_ecnt[tt][b];
    const unsigned int* el = &g_edges[tt][b][0];

    label[tid] = tid;
    if (tid == 0) comp_cnt = 0;

    while (true) {
        __syncthreads();
        if (tid == 0) changed = 0;
        __syncthreads();
        for (int e = tid; e < cnt; e += NA) {
            unsigned int pk = el[e];
            int i = pk >> 16, j = pk & 0xFFFF;
            int li = label[i], lj = label[j];
            if (li < lj) { atomicMin(&label[j], li); changed = 1; }
            else if (lj < li) { atomicMin(&label[i], lj); changed = 1; }
        }
        __syncthreads();
        int l = label[tid];
        int ll = label[l];
        if (ll < l) { label[tid] = ll; changed = 1; }
        __syncthreads();
        if (!changed) break;
    }

    int isrep = (label[tid] == tid) ? 1 : 0;
#pragma unroll
    for (int o = 16; o; o >>= 1) isrep += __shfl_down_sync(0xFFFFFFFFu, isrep, o);
    if ((tid & 31) == 0) atomicAdd(&comp_cnt, isrep);
    __syncthreads();

    if (tid == 0) {
        float comp = (float)comp_cnt;
        float b1 = fmaxf(0.0f, (float)cnt - (float)NA + comp);
        out[b * 6 + tt * 2 + 0] = comp * (1.0f / NA);
        out[b * 6 + tt * 2 + 1] = b1 * (1.0f / NA);
    }
}

// ---------------- launch ----------------
extern "C" void kernel_launch(void* const* d_in, const int* in_sizes, int n_in,
                              void* d_out, int out_size) {
    const float* ret = (const float*)d_in[0];
    float* out = (float*)d_out;
    (void)in_sizes; (void)n_in; (void)out_size;

    cudaFuncSetAttribute(corr_mma_kernel,
                         cudaFuncAttributeMaxDynamicSharedMemorySize, SMEM_DYN);
    cudaFuncSetAttribute(fused_convert_kernel,
                         cudaFuncAttributeMaxDynamicSharedMemorySize, CONV_SMEM);

    { dim3 g(NA / 64, BATCH); fused_convert_kernel<<<g, 256, CONV_SMEM>>>(ret); }
    { dim3 g(NTILE, BATCH);   corr_mma_kernel<<<g, 256, SMEM_DYN>>>(); }
    betti_kernel<<<96, 512>>>(out);
}

// round 10
// speedup vs baseline: 1.8810x; 1.7877x over previous
#include <cuda_runtime.h>
#include <cuda_bf16.h>
#include <cstdint>

// B=32, W=256, N=512, thresholds {0.3,0.5,0.7}
// out: (B,6) fp32 [t0_b0,t0_b1,t1_b0,t1_b1,t2_b0,t2_b1]

#define BATCH 32
#define WIN   256
#define NA    512
#define CAP   131072   // >= 512*511/2
#define KCH   64       // bf16 per K-chunk (128 B rows)
#define NCH   4        // K = 256 (h.h only; band+fixup covers the bf16 error)
#define NSTG  3
#define STAGE_BYTES 24576   // 16KB A(128 rows) + 8KB B(64 rows)
#define SMEM_DYN    (NSTG * STAGE_BYTES)
#define NTILE 20
#define BAND  4.5e-3f       // certified |corr_exact - corr_hh| bound is 3.9e-3
#define SCAP  32768

// ---------------- device scratch ----------------
__device__ __nv_bfloat16 g_h[BATCH][NA][WIN];   // 8 MB
__device__ int   g_ecnt[3][BATCH];
__device__ unsigned int g_edges[3][BATCH][CAP];
__device__ int   g_scnt;
__device__ unsigned int g_susp[SCAP];   // (mask<<23)|(b<<18)|(gi<<9)|gj

__device__ __forceinline__ uint32_t smem_u32(const void* p) {
    uint32_t a;
    asm("{ .reg .u64 t; cvta.to.shared.u64 t, %1; cvt.u32.u64 %0, t; }" : "=r"(a) : "l"(p));
    return a;
}
#define SW128(x) ((x) ^ (((x) >> 3) & 0x70))
#define CP16(dst, src) \
    asm volatile("cp.async.cg.shared.global [%0], [%1], 16;" :: "r"(dst), "l"(src))
#define CPCOMMIT() asm volatile("cp.async.commit_group;" ::: "memory")
#define CPWAIT1()  asm volatile("cp.async.wait_group 1;" ::: "memory")
#define CPWAIT0()  asm volatile("cp.async.wait_group 0;" ::: "memory")

// ------- fused stats + normalize + bf16(h) + transpose -------
// CTA: 32 assets x 256 w. grid (16, 32). 256 threads: a = t&31, q = t>>5 (8 w-chunks).
__global__ void __launch_bounds__(256)
convert_kernel(const float* __restrict__ ret) {
    __shared__ float fsm[WIN][33];              // 33.8 KB
    __shared__ float ps[8][32], ps2[8][32], mean_s[32], inv_s[32];

    const int b = blockIdx.y, n0 = blockIdx.x * 32;
    const int t = threadIdx.x;
    const int a = t & 31, q = t >> 5;

    if (blockIdx.x == 0 && b == 0) {
        if (t < 96) ((int*)g_ecnt)[t] = 0;
        if (t == 96) g_scnt = 0;
    }

    // load 256 w-rows x 32 assets, float4 per thread (8 iters)
    const float* src = ret + (size_t)b * WIN * NA + n0;
#pragma unroll
    for (int it = 0; it < 8; it++) {
        int idx = t + it * 256;
        int w = idx >> 3, sg = idx & 7;
        float4 v4 = *(const float4*)(src + (size_t)w * NA + sg * 4);
        fsm[w][sg * 4 + 0] = v4.x;
        fsm[w][sg * 4 + 1] = v4.y;
        fsm[w][sg * 4 + 2] = v4.z;
        fsm[w][sg * 4 + 3] = v4.w;
    }
    __syncthreads();

    // per-(asset, 32-w chunk) partials, w ascending
    float s = 0.f, s2 = 0.f;
#pragma unroll
    for (int i = 0; i < 32; i++) {
        float x = fsm[q * 32 + i][a];
        s += x; s2 += x * x;
    }
    ps[q][a] = s; ps2[q][a] = s2;
    __syncthreads();

    if (q == 0) {
        float ss = 0.f, ss2 = 0.f;
#pragma unroll
        for (int k = 0; k < 8; k++) { ss += ps[k][a]; ss2 += ps2[k][a]; }
        float mean = ss * (1.0f / WIN);
        float var = fmaxf((ss2 - ss * mean) * (1.0f / (WIN - 1)), 0.0f);
        mean_s[a] = mean;
        inv_s[a] = 1.0f / (sqrtf(var) + 1e-8f);
    }
    __syncthreads();

    const float mean = mean_s[a], inv = inv_s[a];
    __nv_bfloat16* dh = &g_h[b][n0 + a][q * 32];
#pragma unroll
    for (int i8 = 0; i8 < 32; i8 += 8) {
        unsigned int hw[4];
#pragma unroll
        for (int k = 0; k < 4; k++) {
            int w = q * 32 + i8 + 2 * k;
            float x0 = (fsm[w][a] - mean) * inv;
            float x1 = (fsm[w + 1][a] - mean) * inv;
            __nv_bfloat16 h0 = __float2bfloat16(x0);
            __nv_bfloat16 h1 = __float2bfloat16(x1);
            hw[k] = ((unsigned int)__bfloat16_as_ushort(h1) << 16) | __bfloat16_as_ushort(h0);
        }
        *(uint4*)(dh + i8) = make_uint4(hw[0], hw[1], hw[2], hw[3]);
    }
}

// ---------------- corr GEMM: h.h via mma.sync bf16, K=256, 3-stage cp.async --
// CTA tile 128x64, 8 warps (4x2), warp tile 32x32. Grid: 20 upper-tri tiles x 32 b.
__global__ void __launch_bounds__(256, 3)
corr_mma_kernel() {
    extern __shared__ __align__(128) unsigned char dsm[];
    const uint32_t sb = smem_u32(dsm);

    const int TI[NTILE] = {0,0,0,0,0,0,0,0, 1,1,1,1,1,1, 2,2,2,2, 3,3};
    const int TJ[NTILE] = {0,1,2,3,4,5,6,7, 2,3,4,5,6,7, 4,5,6,7, 6,7};
    const int b  = blockIdx.y;
    const int i0 = TI[blockIdx.x] * 128;
    const int j0 = TJ[blockIdx.x] * 64;
    const int t = threadIdx.x;
    const int wid = t >> 5, lane = t & 31;
    const int mw = wid >> 1;       // 0..3 : 32-row group
    const int nw = wid & 1;        // 0..1 : 32-col group

    float acc[2][4][4];
#pragma unroll
    for (int mt = 0; mt < 2; mt++)
#pragma unroll
        for (int nt = 0; nt < 4; nt++)
#pragma unroll
            for (int q = 0; q < 4; q++) acc[mt][nt][q] = 0.f;

    const int arow = t >> 1, ahalf = t & 1;
    const uint32_t aswz = SW128(arow * 128 + ahalf * 64);
    const int brow = t >> 2, bq = t & 3;
    const uint32_t bswz = SW128(brow * 128 + bq * 32);

    const __nv_bfloat16* rowA = &g_h[b][i0 + arow][0];
    const __nv_bfloat16* rowB = &g_h[b][j0 + brow][0];

    auto load_chunk = [&](int c) {
        const uint32_t base = sb + (c % NSTG) * STAGE_BYTES;
        const __nv_bfloat16* sA = rowA + c * KCH + ahalf * 32;
#pragma unroll
        for (int f = 0; f < 4; f++)
            CP16(base + (aswz ^ (f * 16)), sA + f * 8);
        const __nv_bfloat16* sB = rowB + c * KCH + bq * 16;
        CP16(base + 16384 + bswz, sB);
        CP16(base + 16384 + (bswz ^ 16), sB + 8);
        CPCOMMIT();
    };

    load_chunk(0);
    load_chunk(1);

    for (int c = 0; c < NCH; c++) {
        if (c < NCH - 1) CPWAIT1(); else CPWAIT0();
        __syncthreads();

        const uint32_t sbA = sb + (c % NSTG) * STAGE_BYTES;
        const uint32_t sbB = sbA + 16384;
#pragma unroll
        for (int ks = 0; ks < 4; ks++) {
            const int kb = ks * 32;
            uint32_t af[2][4];
#pragma unroll
            for (int mt = 0; mt < 2; mt++) {
                int row = mw * 32 + mt * 16 + ((lane >> 3) & 1) * 8 + (lane & 7);
                int kbyte = kb + (lane >> 4) * 16;
                uint32_t addr = sbA + SW128(row * 128 + kbyte);
                asm volatile("ldmatrix.sync.aligned.m8n8.x4.shared.b16 {%0,%1,%2,%3}, [%4];"
                    : "=r"(af[mt][0]), "=r"(af[mt][1]), "=r"(af[mt][2]), "=r"(af[mt][3])
                    : "r"(addr));
            }
            uint32_t bf[4][2];
#pragma unroll
            for (int np = 0; np < 2; np++) {
                int row = nw * 32 + np * 16 + ((lane >> 4) & 1) * 8 + (lane & 7);
                int kbyte = kb + ((lane >> 3) & 1) * 16;
                uint32_t addr = sbB + SW128(row * 128 + kbyte);
                asm volatile("ldmatrix.sync.aligned.m8n8.x4.shared.b16 {%0,%1,%2,%3}, [%4];"
                    : "=r"(bf[2*np][0]), "=r"(bf[2*np][1]),
                      "=r"(bf[2*np+1][0]), "=r"(bf[2*np+1][1])
                    : "r"(addr));
            }
#pragma unroll
            for (int mt = 0; mt < 2; mt++)
#pragma unroll
                for (int nt = 0; nt < 4; nt++)
                    asm volatile(
                        "mma.sync.aligned.m16n8k16.row.col.f32.bf16.bf16.f32 "
                        "{%0,%1,%2,%3}, {%4,%5,%6,%7}, {%8,%9}, {%0,%1,%2,%3};"
                        : "+f"(acc[mt][nt][0]), "+f"(acc[mt][nt][1]),
                          "+f"(acc[mt][nt][2]), "+f"(acc[mt][nt][3])
                        : "r"(af[mt][0]), "r"(af[mt][1]), "r"(af[mt][2]), "r"(af[mt][3]),
                          "r"(bf[nt][0]), "r"(bf[nt][1]));
        }

        if (c + 2 < NCH) load_chunk(c + 2);
        else CPCOMMIT();   // keep group accounting uniform
    }

    // epilogue: banded threshold -> edges / suspects
    const float TH[3] = {0.3f, 0.5f, 0.7f};
#pragma unroll
    for (int mt = 0; mt < 2; mt++) {
#pragma unroll
        for (int nt = 0; nt < 4; nt++) {
            int gi0 = i0 + mw * 32 + mt * 16 + (lane >> 2);
            int gj0 = j0 + nw * 32 + nt * 8 + 2 * (lane & 3);
#pragma unroll
            for (int q = 0; q < 4; q++) {
                int gi = gi0 + (q >> 1) * 8;
                int gj = gj0 + (q & 1);
                float v = fabsf(acc[mt][nt][q] * (1.0f / 256.0f));
                if (gi < gj && v > TH[0] - BAND) {
                    unsigned int e = ((unsigned int)gi << 16) | (unsigned int)gj;
                    unsigned int mask = 0;
#pragma unroll
                    for (int k = 0; k < 3; k++) {
                        if (v > TH[k] + BAND) {
                            int p = atomicAdd(&g_ecnt[k][b], 1);
                            g_edges[k][b][p] = e;
                        } else if (v > TH[k] - BAND) {
                            mask |= 1u << k;
                        }
                    }
                    if (mask) {
                        int p = atomicAdd(&g_scnt, 1);
                        if (p < SCAP)
                            g_susp[p] = (mask << 23) | ((unsigned int)b << 18)
                                      | ((unsigned int)gi << 9) | (unsigned int)gj;
                    }
                }
            }
        }
    }
}

// ---------------- fixup: fp64 exact corr for in-band pairs ----------------
__global__ void __launch_bounds__(256)
fixup_kernel(const float* __restrict__ ret) {
    __shared__ double rb[256];
    const int t = threadIdx.x;
    const int cnt = min(g_scnt, SCAP);

    for (int s = blockIdx.x; s < cnt; s += gridDim.x) {
        unsigned int wd = g_susp[s];
        int gj = wd & 511, gi = (wd >> 9) & 511;
        int b = (wd >> 18) & 31, mask = (wd >> 23) & 7;

        double xi = (double)ret[((size_t)b * WIN + t) * NA + gi];
        double xj = (double)ret[((size_t)b * WIN + t) * NA + gj];

        double sums[5] = {xi, xi * xi, xj, xj * xj, xi * xj};
        double red[5];
#pragma unroll
        for (int m = 0; m < 5; m++) {
            rb[t] = sums[m];
            __syncthreads();
            for (int off = 128; off; off >>= 1) {
                if (t < off) rb[t] += rb[t + off];
                __syncthreads();
            }
            red[m] = rb[0];
            __syncthreads();
        }

        if (t == 0) {
            double mi = red[0] / 256.0, mj = red[2] / 256.0;
            double vi = (red[1] - red[0] * mi) / 255.0;
            double vj = (red[3] - red[2] * mj) / 255.0;
            double di = sqrt(vi > 0 ? vi : 0) + 1e-8;
            double dj = sqrt(vj > 0 ? vj : 0) + 1e-8;
            double cov = red[4] - 256.0 * mi * mj;
            double v = fabs(cov / (di * dj) / 256.0);
            const double THD[3] = {0.3, 0.5, 0.7};
            unsigned int e = ((unsigned int)gi << 16) | (unsigned int)gj;
            for (int k = 0; k < 3; k++)
                if (((mask >> k) & 1) && v > THD[k]) {
                    int p = atomicAdd(&g_ecnt[k][b], 1);
                    g_edges[k][b][p] = e;
                }
        }
        __syncthreads();
    }
}

// ---------------- components + Betti ----------------
__global__ void __launch_bounds__(512, 1)
betti_kernel(float* __restrict__ out) {
    __shared__ int label[NA];
    __shared__ int changed;
    __shared__ int comp_cnt;

    const int tt = blockIdx.x >> 5;
    const int b  = blockIdx.x & 31;
    const int tid = threadIdx.x;

    const int cnt = g_ecnt[tt][b];
    const unsigned int* el = &g_edges[tt][b][0];

    label[tid] = tid;
    if (tid == 0) comp_cnt = 0;

    while (true) {
        __syncthreads();
        if (tid == 0) changed = 0;
        __syncthreads();
        for (int e = tid; e < cnt; e += NA) {
            unsigned int pk = el[e];
            int i = pk >> 16, j = pk & 0xFFFF;
            int li = label[i], lj = label[j];
            if (li < lj) { atomicMin(&label[j], li); changed = 1; }
            else if (lj < li) { atomicMin(&label[i], lj); changed = 1; }
        }
        __syncthreads();
        int l = label[tid];
        int ll = label[l];
        if (ll < l) { label[tid] = ll; changed = 1; }
        __syncthreads();
        if (!changed) break;
    }

    int isrep = (label[tid] == tid) ? 1 : 0;
#pragma unroll
    for (int o = 16; o; o >>= 1) isrep += __shfl_down_sync(0xFFFFFFFFu, isrep, o);
    if ((tid & 31) == 0) atomicAdd(&comp_cnt, isrep);
    __syncthreads();

    if (tid == 0) {
        float comp = (float)comp_cnt;
        float b1 = fmaxf(0.0f, (float)cnt - (float)NA + comp);
        out[b * 6 + tt * 2 + 0] = comp * (1.0f / NA);
        out[b * 6 + tt * 2 + 1] = b1 * (1.0f / NA);
    }
}

// ---------------- launch ----------------
extern "C" void kernel_launch(void* const* d_in, const int* in_sizes, int n_in,
                              void* d_out, int out_size) {
    const float* ret = (const float*)d_in[0];
    float* out = (float*)d_out;
    (void)in_sizes; (void)n_in; (void)out_size;

    cudaFuncSetAttribute(corr_mma_kernel,
                         cudaFuncAttributeMaxDynamicSharedMemorySize, SMEM_DYN);

    { dim3 g(NA / 32, BATCH); convert_kernel<<<g, 256>>>(ret); }
    { dim3 g(NTILE, BATCH);   corr_mma_kernel<<<g, 256, SMEM_DYN>>>(); }
    fixup_kernel<<<48, 256>>>(ret);
    betti_kernel<<<96, 512>>>(out);
}

// round 11
// speedup vs baseline: 1.9064x; 1.0135x over previous
#include <cuda_runtime.h>
#include <cuda_bf16.h>
#include <cstdint>

// B=32, W=256, N=512, thresholds {0.3,0.5,0.7}
// out: (B,6) fp32 [t0_b0,t0_b1,t1_b0,t1_b1,t2_b0,t2_b1]

#define BATCH 32
#define WIN   256
#define NA    512
#define CAP   131072   // >= 512*511/2
#define KCH   64       // bf16 per K-chunk (128 B rows)
#define NCH   4        // K = 256 (h.h only; band+fixup covers the bf16 error)
#define NSTG  3
#define STAGE_BYTES 24576   // 16KB A(128 rows) + 8KB B(64 rows)
#define SMEM_DYN    (NSTG * STAGE_BYTES)
#define NTILE 20
#define BAND  4.5e-3f       // certified |corr_exact - corr_hh| bound is 3.9e-3
#define SCAP  32768

// ---------------- device scratch ----------------
__device__ __nv_bfloat16 g_h[BATCH][NA][WIN];   // 8 MB
__device__ int   g_ecnt[3][BATCH];
__device__ unsigned int g_edges[3][BATCH][CAP];
__device__ int   g_scnt;
__device__ unsigned int g_susp[SCAP];   // (mask<<23)|(b<<18)|(gi<<9)|gj

__device__ __forceinline__ uint32_t smem_u32(const void* p) {
    uint32_t a;
    asm("{ .reg .u64 t; cvta.to.shared.u64 t, %1; cvt.u32.u64 %0, t; }" : "=r"(a) : "l"(p));
    return a;
}
#define SW128(x) ((x) ^ (((x) >> 3) & 0x70))
#define CP16(dst, src) \
    asm volatile("cp.async.cg.shared.global [%0], [%1], 16;" :: "r"(dst), "l"(src))
#define CPCOMMIT() asm volatile("cp.async.commit_group;" ::: "memory")
#define CPWAIT1()  asm volatile("cp.async.wait_group 1;" ::: "memory")
#define CPWAIT0()  asm volatile("cp.async.wait_group 0;" ::: "memory")

// ------- fused stats + normalize + bf16(h) + transpose -------
// CTA: 32 assets x 256 w. grid (16, 32). 256 threads: a = t&31, q = t>>5.
__global__ void __launch_bounds__(256)
convert_kernel(const float* __restrict__ ret) {
    __shared__ float fsm[WIN][33];              // 33.8 KB
    __shared__ float ps[8][32], ps2[8][32], mean_s[32], inv_s[32];

    const int b = blockIdx.y, n0 = blockIdx.x * 32;
    const int t = threadIdx.x;
    const int a = t & 31, q = t >> 5;

    if (blockIdx.x == 0 && b == 0) {
        if (t < 96) ((int*)g_ecnt)[t] = 0;
        if (t == 96) g_scnt = 0;
    }

    // load 256 w-rows x 32 assets, float4 per thread (8 iters)
    const float* src = ret + (size_t)b * WIN * NA + n0;
#pragma unroll
    for (int it = 0; it < 8; it++) {
        int idx = t + it * 256;
        int w = idx >> 3, sg = idx & 7;
        float4 v4 = *(const float4*)(src + (size_t)w * NA + sg * 4);
        fsm[w][sg * 4 + 0] = v4.x;
        fsm[w][sg * 4 + 1] = v4.y;
        fsm[w][sg * 4 + 2] = v4.z;
        fsm[w][sg * 4 + 3] = v4.w;
    }
    __syncthreads();

    // per-(asset, 32-w chunk) partials, w ascending
    float s = 0.f, s2 = 0.f;
#pragma unroll
    for (int i = 0; i < 32; i++) {
        float x = fsm[q * 32 + i][a];
        s += x; s2 += x * x;
    }
    ps[q][a] = s; ps2[q][a] = s2;
    __syncthreads();

    if (q == 0) {
        float ss = 0.f, ss2 = 0.f;
#pragma unroll
        for (int k = 0; k < 8; k++) { ss += ps[k][a]; ss2 += ps2[k][a]; }
        float mean = ss * (1.0f / WIN);
        float var = fmaxf((ss2 - ss * mean) * (1.0f / (WIN - 1)), 0.0f);
        mean_s[a] = mean;
        inv_s[a] = 1.0f / (sqrtf(var) + 1e-8f);
    }
    __syncthreads();

    const float mean = mean_s[a], inv = inv_s[a];
    __nv_bfloat16* dh = &g_h[b][n0 + a][q * 32];
#pragma unroll
    for (int i8 = 0; i8 < 32; i8 += 8) {
        unsigned int hw[4];
#pragma unroll
        for (int k = 0; k < 4; k++) {
            int w = q * 32 + i8 + 2 * k;
            float x0 = (fsm[w][a] - mean) * inv;
            float x1 = (fsm[w + 1][a] - mean) * inv;
            __nv_bfloat16 h0 = __float2bfloat16(x0);
            __nv_bfloat16 h1 = __float2bfloat16(x1);
            hw[k] = ((unsigned int)__bfloat16_as_ushort(h1) << 16) | __bfloat16_as_ushort(h0);
        }
        *(uint4*)(dh + i8) = make_uint4(hw[0], hw[1], hw[2], hw[3]);
    }
}

// ---------------- corr GEMM: h.h via mma.sync bf16, K=256, 3-stage cp.async --
// CTA tile 128x64, 8 warps (4x2), warp tile 32x32. Grid: 20 upper-tri tiles x 32 b.
__global__ void __launch_bounds__(256, 3)
corr_mma_kernel() {
    extern __shared__ __align__(128) unsigned char dsm[];
    const uint32_t sb = smem_u32(dsm);

    const int TI[NTILE] = {0,0,0,0,0,0,0,0, 1,1,1,1,1,1, 2,2,2,2, 3,3};
    const int TJ[NTILE] = {0,1,2,3,4,5,6,7, 2,3,4,5,6,7, 4,5,6,7, 6,7};
    const int b  = blockIdx.y;
    const int i0 = TI[blockIdx.x] * 128;
    const int j0 = TJ[blockIdx.x] * 64;
    const int t = threadIdx.x;
    const int wid = t >> 5, lane = t & 31;
    const int mw = wid >> 1;       // 0..3 : 32-row group
    const int nw = wid & 1;        // 0..1 : 32-col group

    float acc[2][4][4];
#pragma unroll
    for (int mt = 0; mt < 2; mt++)
#pragma unroll
        for (int nt = 0; nt < 4; nt++)
#pragma unroll
            for (int q = 0; q < 4; q++) acc[mt][nt][q] = 0.f;

    const int arow = t >> 1, ahalf = t & 1;
    const uint32_t aswz = SW128(arow * 128 + ahalf * 64);
    const int brow = t >> 2, bq = t & 3;
    const uint32_t bswz = SW128(brow * 128 + bq * 32);

    const __nv_bfloat16* rowA = &g_h[b][i0 + arow][0];
    const __nv_bfloat16* rowB = &g_h[b][j0 + brow][0];

    auto load_chunk = [&](int c) {
        const uint32_t base = sb + (c % NSTG) * STAGE_BYTES;
        const __nv_bfloat16* sA = rowA + c * KCH + ahalf * 32;
#pragma unroll
        for (int f = 0; f < 4; f++)
            CP16(base + (aswz ^ (f * 16)), sA + f * 8);
        const __nv_bfloat16* sB = rowB + c * KCH + bq * 16;
        CP16(base + 16384 + bswz, sB);
        CP16(base + 16384 + (bswz ^ 16), sB + 8);
        CPCOMMIT();
    };

    load_chunk(0);
    load_chunk(1);

    for (int c = 0; c < NCH; c++) {
        if (c < NCH - 1) CPWAIT1(); else CPWAIT0();
        __syncthreads();

        const uint32_t sbA = sb + (c % NSTG) * STAGE_BYTES;
        const uint32_t sbB = sbA + 16384;
#pragma unroll
        for (int ks = 0; ks < 4; ks++) {
            const int kb = ks * 32;
            uint32_t af[2][4];
#pragma unroll
            for (int mt = 0; mt < 2; mt++) {
                int row = mw * 32 + mt * 16 + ((lane >> 3) & 1) * 8 + (lane & 7);
                int kbyte = kb + (lane >> 4) * 16;
                uint32_t addr = sbA + SW128(row * 128 + kbyte);
                asm volatile("ldmatrix.sync.aligned.m8n8.x4.shared.b16 {%0,%1,%2,%3}, [%4];"
                    : "=r"(af[mt][0]), "=r"(af[mt][1]), "=r"(af[mt][2]), "=r"(af[mt][3])
                    : "r"(addr));
            }
            uint32_t bf[4][2];
#pragma unroll
            for (int np = 0; np < 2; np++) {
                int row = nw * 32 + np * 16 + ((lane >> 4) & 1) * 8 + (lane & 7);
                int kbyte = kb + ((lane >> 3) & 1) * 16;
                uint32_t addr = sbB + SW128(row * 128 + kbyte);
                asm volatile("ldmatrix.sync.aligned.m8n8.x4.shared.b16 {%0,%1,%2,%3}, [%4];"
                    : "=r"(bf[2*np][0]), "=r"(bf[2*np][1]),
                      "=r"(bf[2*np+1][0]), "=r"(bf[2*np+1][1])
                    : "r"(addr));
            }
#pragma unroll
            for (int mt = 0; mt < 2; mt++)
#pragma unroll
                for (int nt = 0; nt < 4; nt++)
                    asm volatile(
                        "mma.sync.aligned.m16n8k16.row.col.f32.bf16.bf16.f32 "
                        "{%0,%1,%2,%3}, {%4,%5,%6,%7}, {%8,%9}, {%0,%1,%2,%3};"
                        : "+f"(acc[mt][nt][0]), "+f"(acc[mt][nt][1]),
                          "+f"(acc[mt][nt][2]), "+f"(acc[mt][nt][3])
                        : "r"(af[mt][0]), "r"(af[mt][1]), "r"(af[mt][2]), "r"(af[mt][3]),
                          "r"(bf[nt][0]), "r"(bf[nt][1]));
        }

        if (c + 2 < NCH) load_chunk(c + 2);
        else CPCOMMIT();   // keep group accounting uniform
    }

    // epilogue: banded threshold -> edges / suspects
    const float TH[3] = {0.3f, 0.5f, 0.7f};
#pragma unroll
    for (int mt = 0; mt < 2; mt++) {
#pragma unroll
        for (int nt = 0; nt < 4; nt++) {
            int gi0 = i0 + mw * 32 + mt * 16 + (lane >> 2);
            int gj0 = j0 + nw * 32 + nt * 8 + 2 * (lane & 3);
#pragma unroll
            for (int q = 0; q < 4; q++) {
                int gi = gi0 + (q >> 1) * 8;
                int gj = gj0 + (q & 1);
                float v = fabsf(acc[mt][nt][q] * (1.0f / 256.0f));
                if (gi < gj && v > TH[0] - BAND) {
                    unsigned int e = ((unsigned int)gi << 16) | (unsigned int)gj;
                    unsigned int mask = 0;
#pragma unroll
                    for (int k = 0; k < 3; k++) {
                        if (v > TH[k] + BAND) {
                            int p = atomicAdd(&g_ecnt[k][b], 1);
                            g_edges[k][b][p] = e;
                        } else if (v > TH[k] - BAND) {
                            mask |= 1u << k;
                        }
                    }
                    if (mask) {
                        int p = atomicAdd(&g_scnt, 1);
                        if (p < SCAP)
                            g_susp[p] = (mask << 23) | ((unsigned int)b << 18)
                                      | ((unsigned int)gi << 9) | (unsigned int)gj;
                    }
                }
            }
        }
    }
}

// ------- components + Betti, with in-block fp64 fixup of in-band suspects ----
__global__ void __launch_bounds__(512, 1)
betti_kernel(const float* __restrict__ ret, float* __restrict__ out) {
    __shared__ int label[NA];
    __shared__ int changed;
    __shared__ int comp_cnt;
    __shared__ unsigned int extra[512];
    __shared__ int extra_cnt;
    __shared__ double wsum[8][5];

    const int tt = blockIdx.x >> 5;
    const int b  = blockIdx.x & 31;
    const int tid = threadIdx.x;

    const int cnt = g_ecnt[tt][b];
    const unsigned int* el = &g_edges[tt][b][0];

    label[tid] = tid;
    if (tid == 0) { comp_cnt = 0; extra_cnt = 0; }
    __syncthreads();

    // resolve suspects for this (tt, b) with exact fp64 correlation
    const int scnt = min(g_scnt, SCAP);
    const double THD[3] = {0.3, 0.5, 0.7};
    for (int s = 0; s < scnt; s++) {
        unsigned int wd = g_susp[s];
        if ((((wd >> 18) & 31) != (unsigned)b) || !((wd >> 23) & (1u << tt)))
            continue;
        int gj = wd & 511, gi = (wd >> 9) & 511;

        double p0 = 0, p1 = 0, p2 = 0, p3 = 0, p4 = 0;
        if (tid < WIN) {
            double xi = (double)ret[((size_t)b * WIN + tid) * NA + gi];
            double xj = (double)ret[((size_t)b * WIN + tid) * NA + gj];
            p0 = xi; p1 = xi * xi; p2 = xj; p3 = xj * xj; p4 = xi * xj;
        }
#pragma unroll
        for (int o = 16; o; o >>= 1) {
            p0 += __shfl_down_sync(0xFFFFFFFFu, p0, o);
            p1 += __shfl_down_sync(0xFFFFFFFFu, p1, o);
            p2 += __shfl_down_sync(0xFFFFFFFFu, p2, o);
            p3 += __shfl_down_sync(0xFFFFFFFFu, p3, o);
            p4 += __shfl_down_sync(0xFFFFFFFFu, p4, o);
        }
        if (tid < WIN && (tid & 31) == 0) {
            wsum[tid >> 5][0] = p0; wsum[tid >> 5][1] = p1;
            wsum[tid >> 5][2] = p2; wsum[tid >> 5][3] = p3;
            wsum[tid >> 5][4] = p4;
        }
        __syncthreads();
        if (tid == 0) {
            double r0 = 0, r1 = 0, r2 = 0, r3 = 0, r4 = 0;
#pragma unroll
            for (int k = 0; k < 8; k++) {
                r0 += wsum[k][0]; r1 += wsum[k][1]; r2 += wsum[k][2];
                r3 += wsum[k][3]; r4 += wsum[k][4];
            }
            double mi = r0 / 256.0, mj = r2 / 256.0;
            double vi = (r1 - r0 * mi) / 255.0;
            double vj = (r3 - r2 * mj) / 255.0;
            double di = sqrt(vi > 0 ? vi : 0) + 1e-8;
            double dj = sqrt(vj > 0 ? vj : 0) + 1e-8;
            double cov = r4 - 256.0 * mi * mj;
            double v = fabs(cov / (di * dj) / 256.0);
            if (v > THD[tt] && extra_cnt < 512)
                extra[extra_cnt++] = ((unsigned int)gi << 16) | (unsigned int)gj;
        }
        __syncthreads();
    }

    // min-label propagation over main + extra edge lists
    while (true) {
        __syncthreads();
        if (tid == 0) changed = 0;
        __syncthreads();
        for (int e = tid; e < cnt; e += NA) {
            unsigned int pk = el[e];
            int i = pk >> 16, j = pk & 0xFFFF;
            int li = label[i], lj = label[j];
            if (li < lj) { atomicMin(&label[j], li); changed = 1; }
            else if (lj < li) { atomicMin(&label[i], lj); changed = 1; }
        }
        for (int e = tid; e < extra_cnt; e += NA) {
            unsigned int pk = extra[e];
            int i = pk >> 16, j = pk & 0xFFFF;
            int li = label[i], lj = label[j];
            if (li < lj) { atomicMin(&label[j], li); changed = 1; }
            else if (lj < li) { atomicMin(&label[i], lj); changed = 1; }
        }
        __syncthreads();
        int l = label[tid];
        int ll = label[l];
        if (ll < l) { label[tid] = ll; changed = 1; }
        __syncthreads();
        if (!changed) break;
    }

    int isrep = (label[tid] == tid) ? 1 : 0;
#pragma unroll
    for (int o = 16; o; o >>= 1) isrep += __shfl_down_sync(0xFFFFFFFFu, isrep, o);
    if ((tid & 31) == 0) atomicAdd(&comp_cnt, isrep);
    __syncthreads();

    if (tid == 0) {
        float comp = (float)comp_cnt;
        float edges = (float)(cnt + extra_cnt);
        float b1 = fmaxf(0.0f, edges - (float)NA + comp);
        out[b * 6 + tt * 2 + 0] = comp * (1.0f / NA);
        out[b * 6 + tt * 2 + 1] = b1 * (1.0f / NA);
    }
}

// ---------------- launch ----------------
extern "C" void kernel_launch(void* const* d_in, const int* in_sizes, int n_in,
                              void* d_out, int out_size) {
    const float* ret = (const float*)d_in[0];
    float* out = (float*)d_out;
    (void)in_sizes; (void)n_in; (void)out_size;

    cudaFuncSetAttribute(corr_mma_kernel,
                         cudaFuncAttributeMaxDynamicSharedMemorySize, SMEM_DYN);

    { dim3 g(NA / 32, BATCH); convert_kernel<<<g, 256>>>(ret); }
    { dim3 g(NTILE, BATCH);   corr_mma_kernel<<<g, 256, SMEM_DYN>>>(); }
    betti_kernel<<<96, 512>>>(ret, out);
}